// round 17
// baseline (speedup 1.0000x reference)
#include <cuda_runtime.h>
#include <cuda_fp16.h>

#define Nn 80000
#define Ee 1280000
#define Cc 64
#define NCELEM (Nn * Cc)
#define CAP 64   // bucket capacity (deg: mean 16, sigma 4 -> 12 sigma headroom)

// Scratch (static device arrays; no allocation anywhere)
__device__ __align__(256) __half g_h[NCELEM];   // h' = dis[row] * (x @ W), fp16
__device__ __align__(256) float  g_xbuf[NCELEM];
__device__ float  g_dis[Nn];
__device__ int    g_cnt[Nn];
__device__ __align__(16) int2 g_bkt[(size_t)Nn * CAP];  // {src, w_bits}
__device__ double g_part[128];
__device__ float  g_mv[2];   // mean, rstd of last LN

// ---------------------------------------------------------------------------
__device__ __forceinline__ unsigned smem_u32(const void* p) {
    return (unsigned)__cvta_generic_to_shared(p);
}
__device__ __forceinline__ void ldsm_x4(unsigned* r, unsigned addr) {
    asm volatile("ldmatrix.sync.aligned.m8n8.x4.shared.b16 {%0,%1,%2,%3}, [%4];\n"
                 : "=r"(r[0]), "=r"(r[1]), "=r"(r[2]), "=r"(r[3]) : "r"(addr));
}
__device__ __forceinline__ void ldsm_x2t(unsigned* r, unsigned addr) {
    asm volatile("ldmatrix.sync.aligned.m8n8.x2.trans.shared.b16 {%0,%1}, [%2];\n"
                 : "=r"(r[0]), "=r"(r[1]) : "r"(addr));
}
__device__ __forceinline__ void mma16816(float* c, const unsigned* a, const unsigned* b) {
    asm volatile(
        "mma.sync.aligned.m16n8k16.row.col.f32.f16.f16.f32 "
        "{%0,%1,%2,%3}, {%4,%5,%6,%7}, {%8,%9}, {%0,%1,%2,%3};\n"
        : "+f"(c[0]), "+f"(c[1]), "+f"(c[2]), "+f"(c[3])
        : "r"(a[0]), "r"(a[1]), "r"(a[2]), "r"(a[3]), "r"(b[0]), "r"(b[1]));
}

// ---------------------------------------------------------------------------
// prep_k: first ZB blocks zero g_cnt; remaining blocks stream the tuple tail
// (edge_index -> f32, edge_attr).
#define ZB ((Nn + 255) / 256)
__global__ void prep_k(const int* __restrict__ ei, const float* __restrict__ ea,
                       float* __restrict__ out, int out_size) {
    int blk = blockIdx.x;
    if (blk < ZB) {
        int i = blk * 256 + threadIdx.x;
        if (i < Nn) g_cnt[i] = 0;
        return;
    }
    int i = (blk - ZB) * 256 + threadIdx.x;  // over 3*Ee/4 vec4 items
    const int Q2 = 2 * Ee / 4, Q3 = 3 * Ee / 4;
    if (i < Q2) {
        int4 v = ((const int4*)ei)[i];
        int o = NCELEM + i * 4;
        if (o + 3 < out_size)
            ((float4*)out)[o >> 2] = make_float4((float)v.x, (float)v.y,
                                                 (float)v.z, (float)v.w);
    } else if (i < Q3) {
        int j = i - Q2;
        float4 f = ((const float4*)ea)[j];
        int o = NCELEM + 2 * Ee + j * 4;
        if (o + 3 < out_size) ((float4*)out)[o >> 2] = f;
    }
}

// Eight edges per thread: 8 independent random atomic+store chains.
__global__ void fill_k(const int* __restrict__ src, const int* __restrict__ dst,
                       const float* __restrict__ ea) {
    int t = blockIdx.x * blockDim.x + threadIdx.x;  // grid exact Ee/8/256
    int e = t * 8;
#pragma unroll
    for (int u = 0; u < 8; u += 4) {
        int4   d4 = *(const int4*)(dst + e + u);
        int4   s4 = *(const int4*)(src + e + u);
        float4 w4 = *(const float4*)(ea + e + u);
        int p0 = atomicAdd(&g_cnt[d4.x], 1);
        int p1 = atomicAdd(&g_cnt[d4.y], 1);
        int p2 = atomicAdd(&g_cnt[d4.z], 1);
        int p3 = atomicAdd(&g_cnt[d4.w], 1);
        if (p0 < CAP) g_bkt[((size_t)d4.x << 6) + p0] = make_int2(s4.x, __float_as_int(w4.x));
        if (p1 < CAP) g_bkt[((size_t)d4.y << 6) + p1] = make_int2(s4.y, __float_as_int(w4.y));
        if (p2 < CAP) g_bkt[((size_t)d4.z << 6) + p2] = make_int2(s4.z, __float_as_int(w4.z));
        if (p3 < CAP) g_bkt[((size_t)d4.w << 6) + p3] = make_int2(s4.w, __float_as_int(w4.w));
    }
}

__global__ __launch_bounds__(256) void dis_k() {
    int lane = threadIdx.x & 31, wid = threadIdx.x >> 5;
    int node = blockIdx.x * 8 + wid;  // grid exact Nn/8
    int cnt = min(g_cnt[node], CAP);
    float s = 0.f;
    for (int i = lane; i < cnt; i += 32)
        s += __int_as_float(g_bkt[((size_t)node << 6) + i].y);
#pragma unroll
    for (int o = 16; o; o >>= 1) s += __shfl_xor_sync(0xffffffffu, s, o);
    if (lane == 0)
        g_dis[node] = s > 0.f ? rsqrtf(fmaxf(s, 1e-12f)) : 0.f;
}

// ---------------------------------------------------------------------------
// h' = dis .* (LN?(X) @ W), fp16 out, HMMA. 128 rows x 64 cols per block.
__global__ __launch_bounds__(256) void gemm_k(const float* __restrict__ Xext,
                                              const float* __restrict__ W,
                                              const float* __restrict__ lnw,
                                              const float* __restrict__ lnb) {
    __shared__ __align__(16) __half Xh[128][72];  // 144B row stride (16B-mult)
    __shared__ __align__(16) __half Wh[64][72];
    const float* X = Xext ? Xext : g_xbuf;
    int tid  = threadIdx.x;
    int row0 = blockIdx.x * 128;
    int wid = tid >> 5, lane = tid & 31;
    int m0 = wid * 16;
    int gid = lane >> 2, tig = lane & 3;
    int rl0 = m0 + gid;

    // Hoisted epilogue operands: in flight during load + MMA phases.
    float d0 = g_dis[row0 + rl0], d1 = g_dis[row0 + rl0 + 8];

    if (blockIdx.x == 0 && tid < 128) g_part[tid] = 0.0;  // reset stats partials

    float m = 0.f, rs = 1.f;
    if (lnw) { m = g_mv[0]; rs = g_mv[1]; }

    for (int i = tid; i < 1024; i += 256) {   // W: 64x64 floats
        float4 w4 = ((const float4*)W)[i];
        int r = i >> 4, c = (i & 15) * 4;
        __half2* p = (__half2*)&Wh[r][c];
        p[0] = __floats2half2_rn(w4.x, w4.y);
        p[1] = __floats2half2_rn(w4.z, w4.w);
    }
    for (int i = tid; i < 2048; i += 256) {   // X tile, lazy LN on load
        float4 x4 = ((const float4*)(X + (size_t)row0 * 64))[i];
        int r = i >> 4, c = (i & 15) * 4;
        if (lnw) {
            x4.x = (x4.x - m) * rs * lnw[c]     + lnb[c];
            x4.y = (x4.y - m) * rs * lnw[c + 1] + lnb[c + 1];
            x4.z = (x4.z - m) * rs * lnw[c + 2] + lnb[c + 2];
            x4.w = (x4.w - m) * rs * lnw[c + 3] + lnb[c + 3];
        }
        __half2* p = (__half2*)&Xh[r][c];
        p[0] = __floats2half2_rn(x4.x, x4.y);
        p[1] = __floats2half2_rn(x4.z, x4.w);
    }
    __syncthreads();

    float cacc[8][4];
#pragma unroll
    for (int t = 0; t < 8; t++)
#pragma unroll
        for (int q = 0; q < 4; q++) cacc[t][q] = 0.f;

#pragma unroll
    for (int kc = 0; kc < 4; kc++) {
        int k0 = kc * 16;
        unsigned a[4];
        ldsm_x4(a, smem_u32(&Xh[m0 + (lane & 15)][k0 + ((lane >> 4) << 3)]));
#pragma unroll
        for (int nt = 0; nt < 8; nt++) {
            unsigned b[2];
            ldsm_x2t(b, smem_u32(&Wh[k0 + (lane & 15)][nt * 8]));
            mma16816(cacc[nt], a, b);
        }
    }
    __syncthreads();  // done reading Xh/Wh; reuse Xh as C staging

#pragma unroll
    for (int nt = 0; nt < 8; nt++) {
        int colb = nt * 8 + tig * 2;
        *(__half2*)&Xh[rl0][colb] =
            __floats2half2_rn(cacc[nt][0] * d0, cacc[nt][1] * d0);
        *(__half2*)&Xh[rl0 + 8][colb] =
            __floats2half2_rn(cacc[nt][2] * d1, cacc[nt][3] * d1);
    }
    __syncthreads();

    for (int j = tid; j < 1024; j += 256) { // 128 rows x 8 segs of 16B
        int row = j >> 3, seg = j & 7;
        uint4 v = *(const uint4*)&Xh[row][seg * 8];
        *(uint4*)(g_h + (size_t)(row0 + row) * 64 + seg * 8) = v;
    }
}

// ---------------------------------------------------------------------------
// Gather, smem-staged edges, hoisted epilogue loads. Stage 1: warp-coalesced
// bucket staging (4 nodes/warp). Epilogue operands (residual, bias, LN, dis)
// issued immediately after so they overlap the edge walk. Stage 2: per-quarter
// edge walk from smem, MLP=8.
__global__ __launch_bounds__(256) void gather_k(const float* __restrict__ xin,
                                                const float* __restrict__ b,
                                                const float* __restrict__ lnw,
                                                const float* __restrict__ lnb,
                                                float* __restrict__ outp,
                                                int mode, int out_size) {
    __shared__ __align__(16) int2 sbkt[32][CAP];   // 16 KB
    int lane = threadIdx.x & 31;
    int wid  = threadIdx.x >> 5;
    int qt   = lane >> 3;
    int ql   = lane & 7;
    int nloc = wid * 4;                          // local node index base
    int node = blockIdx.x * 32 + nloc + qt;      // grid exact Nn/32
    int c8   = ql * 8;

    // Stage 1: warp-coalesced bucket staging for this warp's 4 nodes.
#pragma unroll
    for (int q4 = 0; q4 < 4; q4++) {
        int nd = blockIdx.x * 32 + nloc + q4;
        int c  = min(g_cnt[nd], CAP);
        if (lane < c)      sbkt[nloc + q4][lane]      = g_bkt[((size_t)nd << 6) + lane];
        if (lane + 32 < c) sbkt[nloc + q4][lane + 32] = g_bkt[((size_t)nd << 6) + lane + 32];
    }

    // Hoisted epilogue operand loads — overlap the entire edge walk.
    float ds = g_dis[node];
    const float* xi = xin ? xin : g_xbuf;
    float4 xv0 = *(const float4*)(xi + (size_t)node * 64 + c8);
    float4 xv1 = *(const float4*)(xi + (size_t)node * 64 + c8 + 4);
    float4 lw0 = make_float4(0.f, 0.f, 0.f, 0.f), lw1 = lw0, lb0 = lw0, lb1 = lw0;
    if (lnw) {
        lw0 = *(const float4*)(lnw + c8); lw1 = *(const float4*)(lnw + c8 + 4);
        lb0 = *(const float4*)(lnb + c8); lb1 = *(const float4*)(lnb + c8 + 4);
    }
    float4 bb0 = *(const float4*)(b + c8), bb1 = *(const float4*)(b + c8 + 4);
    int cq = min(g_cnt[node], CAP);
    __syncwarp();

    // Stage 2: per-quarter edge walk from smem, MLP=8.
    float acc[8];
#pragma unroll
    for (int k = 0; k < 8; k++) acc[k] = 0.f;

    const int2* ebase = sbkt[nloc + qt];
    int j = 0;
    for (; j + 8 <= cq; j += 8) {
        uint4 hv[8];
        float w[8];
#pragma unroll
        for (int u = 0; u < 8; u++) {
            int2 e = ebase[j + u];
            w[u] = __int_as_float(e.y);
            hv[u] = *(const uint4*)(g_h + (size_t)e.x * 64 + c8);
        }
#pragma unroll
        for (int u = 0; u < 8; u++) {
            float2 p0 = __half22float2(*(__half2*)&hv[u].x);
            float2 p1 = __half22float2(*(__half2*)&hv[u].y);
            float2 p2 = __half22float2(*(__half2*)&hv[u].z);
            float2 p3 = __half22float2(*(__half2*)&hv[u].w);
            acc[0] = fmaf(w[u], p0.x, acc[0]); acc[1] = fmaf(w[u], p0.y, acc[1]);
            acc[2] = fmaf(w[u], p1.x, acc[2]); acc[3] = fmaf(w[u], p1.y, acc[3]);
            acc[4] = fmaf(w[u], p2.x, acc[4]); acc[5] = fmaf(w[u], p2.y, acc[5]);
            acc[6] = fmaf(w[u], p3.x, acc[6]); acc[7] = fmaf(w[u], p3.y, acc[7]);
        }
    }
    for (; j < cq; j++) {
        int2 e = ebase[j];
        float w = __int_as_float(e.y);
        uint4 hv = *(const uint4*)(g_h + (size_t)e.x * 64 + c8);
        float2 p0 = __half22float2(*(__half2*)&hv.x);
        float2 p1 = __half22float2(*(__half2*)&hv.y);
        float2 p2 = __half22float2(*(__half2*)&hv.z);
        float2 p3 = __half22float2(*(__half2*)&hv.w);
        acc[0] = fmaf(w, p0.x, acc[0]); acc[1] = fmaf(w, p0.y, acc[1]);
        acc[2] = fmaf(w, p1.x, acc[2]); acc[3] = fmaf(w, p1.y, acc[3]);
        acc[4] = fmaf(w, p2.x, acc[4]); acc[5] = fmaf(w, p2.y, acc[5]);
        acc[6] = fmaf(w, p3.x, acc[6]); acc[7] = fmaf(w, p3.y, acc[7]);
    }
    __syncwarp();

    if (lnw) {  // lazy LN of previous layer on residual path
        float m0 = g_mv[0], rs0 = g_mv[1];
        xv0.x = (xv0.x - m0) * rs0 * lw0.x + lb0.x;
        xv0.y = (xv0.y - m0) * rs0 * lw0.y + lb0.y;
        xv0.z = (xv0.z - m0) * rs0 * lw0.z + lb0.z;
        xv0.w = (xv0.w - m0) * rs0 * lw0.w + lb0.w;
        xv1.x = (xv1.x - m0) * rs0 * lw1.x + lb1.x;
        xv1.y = (xv1.y - m0) * rs0 * lw1.y + lb1.y;
        xv1.z = (xv1.z - m0) * rs0 * lw1.z + lb1.z;
        xv1.w = (xv1.w - m0) * rs0 * lw1.w + lb1.w;
    }
    float4 v0 = make_float4(xv0.x + acc[0] * ds + bb0.x, xv0.y + acc[1] * ds + bb0.y,
                            xv0.z + acc[2] * ds + bb0.z, xv0.w + acc[3] * ds + bb0.w);
    float4 v1 = make_float4(xv1.x + acc[4] * ds + bb1.x, xv1.y + acc[5] * ds + bb1.y,
                            xv1.z + acc[6] * ds + bb1.z, xv1.w + acc[7] * ds + bb1.w);

    if (mode == 0) {
        v0.x = fmaxf(v0.x, 0.f); v0.y = fmaxf(v0.y, 0.f);
        v0.z = fmaxf(v0.z, 0.f); v0.w = fmaxf(v0.w, 0.f);
        v1.x = fmaxf(v1.x, 0.f); v1.y = fmaxf(v1.y, 0.f);
        v1.z = fmaxf(v1.z, 0.f); v1.w = fmaxf(v1.w, 0.f);
        *(float4*)(g_xbuf + (size_t)node * 64 + c8)     = v0;
        *(float4*)(g_xbuf + (size_t)node * 64 + c8 + 4) = v1;
        float s1 = ((v0.x + v0.y) + (v0.z + v0.w)) + ((v1.x + v1.y) + (v1.z + v1.w));
        float s2 = (v0.x * v0.x + v0.y * v0.y) + (v0.z * v0.z + v0.w * v0.w)
                 + (v1.x * v1.x + v1.y * v1.y) + (v1.z * v1.z + v1.w * v1.w);
#pragma unroll
        for (int o = 16; o; o >>= 1) {  // stats are global: full warp fine
            s1 += __shfl_xor_sync(0xffffffffu, s1, o);
            s2 += __shfl_xor_sync(0xffffffffu, s2, o);
        }
        __shared__ float sh1[8], sh2[8];
        if (lane == 0) { sh1[wid] = s1; sh2[wid] = s2; }
        __syncthreads();
        if (threadIdx.x == 0) {
            float a = 0.f, c = 0.f;
#pragma unroll
            for (int q = 0; q < 8; q++) { a += sh1[q]; c += sh2[q]; }
            int slot = blockIdx.x & 63;
            atomicAdd(&g_part[slot], (double)a);
            atomicAdd(&g_part[64 + slot], (double)c);
        }
    } else {
        int o = node * 64 + c8;
        if (o + 7 < out_size) {
            *(float4*)(outp + o)     = v0;
            *(float4*)(outp + o + 4) = v1;
        }
    }
}

// Reduce spread partials -> mean, rstd (for NEXT layer's lazy LN).
__global__ void stats_k() {
    int t = threadIdx.x;  // 64 threads
    double a = g_part[t], c = g_part[64 + t];
#pragma unroll
    for (int o = 16; o; o >>= 1) {
        a += __shfl_xor_sync(0xffffffffu, a, o);
        c += __shfl_xor_sync(0xffffffffu, c, o);
    }
    __shared__ double s[4];
    if ((t & 31) == 0) { s[(t >> 5) * 2] = a; s[(t >> 5) * 2 + 1] = c; }
    __syncthreads();
    if (t == 0) {
        double A = s[0] + s[2], C = s[1] + s[3];
        double mean = A / (double)NCELEM;
        double var  = C / (double)NCELEM - mean * mean;
        if (var < 0.0) var = 0.0;
        g_mv[0] = (float)mean;
        g_mv[1] = 1.0f / ((float)sqrt(var) + 1e-5f);
    }
}

// ---------------------------------------------------------------------------
extern "C" void kernel_launch(void* const* d_in, const int* in_sizes, int n_in,
                              void* d_out, int out_size) {
    const float* x  = (const float*)d_in[0];
    const int*   ei = (const int*)d_in[1];
    const float* ea = (const float*)d_in[2];
    const float* Wl[3]  = {(const float*)d_in[3], (const float*)d_in[5], (const float*)d_in[7]};
    const float* bl[3]  = {(const float*)d_in[4], (const float*)d_in[6], (const float*)d_in[8]};
    const float* lnw[2] = {(const float*)d_in[9],  (const float*)d_in[11]};
    const float* lnb[2] = {(const float*)d_in[10], (const float*)d_in[12]};
    float* out = (float*)d_out;
    const int* src = ei;
    const int* dst = ei + Ee;

    int tail_blocks = (3 * Ee / 4 + 255) / 256;
    prep_k<<<ZB + tail_blocks, 256>>>(ei, ea, out, out_size);  // zero cnt + tuple tail
    fill_k<<<Ee / 8 / 256, 256>>>(src, dst, ea);
    dis_k<<<Nn / 8, 256>>>();

    for (int l = 0; l < 3; l++) {
        const float* xin = (l == 0) ? x : nullptr;           // null -> g_xbuf
        const float* lw  = (l == 0) ? nullptr : lnw[l - 1];  // lazy LN params
        const float* lb  = (l == 0) ? nullptr : lnb[l - 1];
        gemm_k<<<Nn / 128, 256>>>(xin, Wl[l], lw, lb);       // resets partials
        if (l < 2) {
            gather_k<<<Nn / 32, 256>>>(xin, bl[l], lw, lb, nullptr, 0, 0);
            stats_k<<<1, 64>>>();
        } else {
            gather_k<<<Nn / 32, 256>>>(xin, bl[l], lw, lb, out, 1, out_size);
        }
    }
}